// round 1
// baseline (speedup 1.0000x reference)
#include <cuda_runtime.h>
#include <cuda_bf16.h>

// ChamferDistance: B=8, N=4096, D=3.
// out = mean_j min_i ||x_i - y_j||^2 + mean_i min_j ||x_i - y_j||^2
//
// Strategy: brute-force pairwise with the dot-product identity
//   ||x - y||^2 = xd + yd - 2 x.y
// Per query point, minimize (yd_j - 2 x.y_j) over the target set, add xd once.
// Target points tiled through shared memory as float4 {y0,y1,y2,yd} so the
// inner loop is 1 broadcast LDS.128 + 4 FFMA + 1 FMNMX per pair.
// Both directions run in one launch via gridDim.z.
// Deterministic two-stage sum reduction (no float atomics).

#define CD_B 8
#define CD_N 4096
#define CD_TPB 256
#define CD_TILE 2048          // y points per smem tile (32 KB as float4)
#define CD_NBLK_X (CD_N / CD_TPB)       // 16
#define CD_NPART (2 * CD_B * CD_NBLK_X) // 256 partial sums

__device__ float g_cd_partials[CD_NPART];

__global__ __launch_bounds__(CD_TPB)
void chamfer_pass_kernel(const float* __restrict__ p1,
                         const float* __restrict__ p2) {
    __shared__ float4 sy[CD_TILE];
    __shared__ float red[CD_TPB];

    const int tid = threadIdx.x;
    const int b   = blockIdx.y;
    const int dir = blockIdx.z;

    // dir 0: queries = p1 (x), targets = p2 (y)  -> min over j for each i
    // dir 1: queries = p2, targets = p1          -> min over i for each j
    const float* __restrict__ src = (dir == 0) ? p1 : p2;
    const float* __restrict__ tgt = (dir == 0) ? p2 : p1;

    const int i = blockIdx.x * CD_TPB + tid;
    const float* xp = src + ((size_t)b * CD_N + i) * 3;
    const float x0 = xp[0];
    const float x1 = xp[1];
    const float x2 = xp[2];

    float minv = 3.402823466e38f;

    for (int c = 0; c < CD_N; c += CD_TILE) {
        // Cooperative load of target tile into smem, precompute yd.
        #pragma unroll
        for (int j = tid; j < CD_TILE; j += CD_TPB) {
            const float* yp = tgt + ((size_t)b * CD_N + c + j) * 3;
            float y0 = yp[0], y1 = yp[1], y2 = yp[2];
            sy[j] = make_float4(y0, y1, y2, y0 * y0 + y1 * y1 + y2 * y2);
        }
        __syncthreads();

        #pragma unroll 8
        for (int j = 0; j < CD_TILE; j++) {
            float4 q = sy[j];               // broadcast: all lanes same j
            float zz = x0 * q.x;
            zz = fmaf(x1, q.y, zz);
            zz = fmaf(x2, q.z, zz);
            float d = fmaf(zz, -2.0f, q.w); // yd - 2*x.y
            minv = fminf(minv, d);
        }
        __syncthreads();
    }

    const float xd = x0 * x0 + x1 * x1 + x2 * x2;
    float val = minv + xd;                  // min_j ||x_i - y_j||^2

    // Deterministic block-sum.
    red[tid] = val;
    __syncthreads();
    #pragma unroll
    for (int s = CD_TPB / 2; s > 0; s >>= 1) {
        if (tid < s) red[tid] += red[tid + s];
        __syncthreads();
    }
    if (tid == 0) {
        int idx = (dir * CD_B + b) * CD_NBLK_X + blockIdx.x;
        g_cd_partials[idx] = red[0];
    }
}

__global__ __launch_bounds__(CD_NPART)
void chamfer_reduce_kernel(float* __restrict__ out) {
    __shared__ float red[CD_NPART];
    const int tid = threadIdx.x;
    red[tid] = g_cd_partials[tid];
    __syncthreads();
    #pragma unroll
    for (int s = CD_NPART / 2; s > 0; s >>= 1) {
        if (tid < s) red[tid] += red[tid + s];
        __syncthreads();
    }
    if (tid == 0) {
        // Each direction's mean divides by B*N; sum of both sums / (B*N).
        out[0] = red[0] * (1.0f / ((float)CD_B * (float)CD_N));
    }
}

extern "C" void kernel_launch(void* const* d_in, const int* in_sizes, int n_in,
                              void* d_out, int out_size) {
    (void)in_sizes; (void)n_in; (void)out_size;
    const float* p1 = (const float*)d_in[0];
    const float* p2 = (const float*)d_in[1];
    float* out = (float*)d_out;

    dim3 grid(CD_NBLK_X, CD_B, 2);
    chamfer_pass_kernel<<<grid, CD_TPB>>>(p1, p2);
    chamfer_reduce_kernel<<<1, CD_NPART>>>(out);
}

// round 2
// speedup vs baseline: 1.3988x; 1.3988x over previous
#include <cuda_runtime.h>
#include <cuda_bf16.h>

// ChamferDistance: B=8, N=4096, D=3.
// out = mean_j min_i ||x_i - y_j||^2 + mean_i min_j ||x_i - y_j||^2
//
// Round 2: packed f32x2 FFMA inner loop.
//   d_j = yd_j - 2 x.y_j  computed as a 3-deep packed FFMA chain with the
//   (-2) folded into the query coords: 3 fma.rn.f32x2 per 2 target points.
// Shared tile stored pair-interleaved so one LDS.128 yields two packed
// operands (ulonglong2) with zero repacking.
// Q=2 queries per thread amortize the LDS traffic below the fma-pipe bound.
// Reduction fused via last-block-done (deterministic fixed-order sum).

#define CD_B 8
#define CD_N 4096
#define CD_TPB 256
#define CD_Q 2
#define CD_TILE_PTS 2048                      // target points per smem tile (32KB)
#define CD_TILE_PAIRS (CD_TILE_PTS / 2)       // 1024
#define CD_NBLK_X (CD_N / (CD_TPB * CD_Q))    // 8
#define CD_NPART (2 * CD_B * CD_NBLK_X)       // 128 partial sums
#define CD_NBLOCKS CD_NPART                   // 128 total blocks

__device__ float g_cd_partials[CD_NPART];
__device__ unsigned int g_cd_count;

typedef unsigned long long u64;

__device__ __forceinline__ u64 pack2(float v) {
    u64 r;
    unsigned int u = __float_as_uint(v);
    asm("mov.b64 %0, {%1, %1};" : "=l"(r) : "r"(u));
    return r;
}

__device__ __forceinline__ u64 fma2(u64 a, u64 b, u64 c) {
    u64 d;
    asm("fma.rn.f32x2 %0, %1, %2, %3;" : "=l"(d) : "l"(a), "l"(b), "l"(c));
    return d;
}

__device__ __forceinline__ void unpack2(u64 v, float& lo, float& hi) {
    unsigned int l, h;
    asm("mov.b64 {%0, %1}, %2;" : "=r"(l), "=r"(h) : "l"(v));
    lo = __uint_as_float(l);
    hi = __uint_as_float(h);
}

__global__ __launch_bounds__(CD_TPB)
void chamfer_kernel(const float* __restrict__ p1,
                    const float* __restrict__ p2,
                    float* __restrict__ out) {
    __shared__ float4 sy[CD_TILE_PTS];   // pair-interleaved: {y0e,y0o,y1e,y1o},{y2e,y2o,yde,ydo}
    __shared__ float red[CD_TPB];
    __shared__ int s_last;

    const int tid = threadIdx.x;
    const int b   = blockIdx.y;
    const int dir = blockIdx.z;

    const float* __restrict__ src = dir ? p2 : p1;
    const float* __restrict__ tgt = dir ? p1 : p2;

    // Load Q query points per thread; fold -2 into coords, pre-pack f32x2.
    float xd[CD_Q];
    u64 xq0[CD_Q], xq1[CD_Q], xq2[CD_Q];
    float mlo[CD_Q], mhi[CD_Q];
    #pragma unroll
    for (int q = 0; q < CD_Q; q++) {
        const int i = blockIdx.x * (CD_TPB * CD_Q) + q * CD_TPB + tid;
        const float* xp = src + ((size_t)b * CD_N + i) * 3;
        const float x0 = xp[0], x1 = xp[1], x2 = xp[2];
        xd[q]  = x0 * x0 + x1 * x1 + x2 * x2;
        xq0[q] = pack2(-2.0f * x0);
        xq1[q] = pack2(-2.0f * x1);
        xq2[q] = pack2(-2.0f * x2);
        mlo[q] = 3.402823466e38f;
        mhi[q] = 3.402823466e38f;
    }

    const ulonglong2* __restrict__ syu = reinterpret_cast<const ulonglong2*>(sy);

    for (int c = 0; c < CD_N; c += CD_TILE_PTS) {
        // Cooperative pair-interleaved tile load with yd precompute.
        #pragma unroll
        for (int p = tid; p < CD_TILE_PAIRS; p += CD_TPB) {
            const float* yp = tgt + ((size_t)b * CD_N + c + 2 * p) * 3;
            float e0 = yp[0], e1 = yp[1], e2 = yp[2];
            float o0 = yp[3], o1 = yp[4], o2 = yp[5];
            sy[2 * p]     = make_float4(e0, o0, e1, o1);
            sy[2 * p + 1] = make_float4(e2, o2,
                                        e0 * e0 + e1 * e1 + e2 * e2,
                                        o0 * o0 + o1 * o1 + o2 * o2);
        }
        __syncthreads();

        #pragma unroll 4
        for (int p = 0; p < CD_TILE_PAIRS; p++) {
            ulonglong2 A = syu[2 * p];       // A.x = y0 pair, A.y = y1 pair
            ulonglong2 Bv = syu[2 * p + 1];  // Bv.x = y2 pair, Bv.y = yd pair
            #pragma unroll
            for (int q = 0; q < CD_Q; q++) {
                u64 d = fma2(xq2[q], Bv.x, Bv.y);   // yd - 2 x2 y2
                d = fma2(xq1[q], A.y, d);
                d = fma2(xq0[q], A.x, d);
                float dlo, dhi;
                unpack2(d, dlo, dhi);
                mlo[q] = fminf(mlo[q], dlo);
                mhi[q] = fminf(mhi[q], dhi);
            }
        }
        __syncthreads();
    }

    float acc = 0.0f;
    #pragma unroll
    for (int q = 0; q < CD_Q; q++)
        acc += fminf(mlo[q], mhi[q]) + xd[q];

    // Deterministic block sum.
    red[tid] = acc;
    __syncthreads();
    #pragma unroll
    for (int s = CD_TPB / 2; s > 0; s >>= 1) {
        if (tid < s) red[tid] += red[tid + s];
        __syncthreads();
    }

    // Last-block-done final reduction (deterministic fixed-order read).
    if (tid == 0) {
        const int idx = (dir * CD_B + b) * CD_NBLK_X + blockIdx.x;
        g_cd_partials[idx] = red[0];
        __threadfence();
        unsigned int t = atomicAdd(&g_cd_count, 1u);
        s_last = (t == CD_NBLOCKS - 1);
    }
    __syncthreads();

    if (s_last) {
        float v = (tid < CD_NPART) ? g_cd_partials[tid] : 0.0f;
        red[tid] = v;
        __syncthreads();
        #pragma unroll
        for (int s = CD_TPB / 2; s > 0; s >>= 1) {
            if (tid < s) red[tid] += red[tid + s];
            __syncthreads();
        }
        if (tid == 0) {
            out[0] = red[0] * (1.0f / ((float)CD_B * (float)CD_N));
            g_cd_count = 0;   // reset for graph replay
        }
    }
}

extern "C" void kernel_launch(void* const* d_in, const int* in_sizes, int n_in,
                              void* d_out, int out_size) {
    (void)in_sizes; (void)n_in; (void)out_size;
    const float* p1 = (const float*)d_in[0];
    const float* p2 = (const float*)d_in[1];
    float* out = (float*)d_out;

    dim3 grid(CD_NBLK_X, CD_B, 2);
    chamfer_kernel<<<grid, CD_TPB>>>(p1, p2, out);
}

// round 3
// speedup vs baseline: 1.6138x; 1.1538x over previous
#include <cuda_runtime.h>
#include <cuda_bf16.h>

// ChamferDistance: B=8, N=4096, D=3.
// Round 3: the round-2 kernel was LDS-crossbar-bound (broadcast LDS.128 moves
// a full 512B wavefront set: 4 SM-cyc each; 2 per pair-iter = 8 SM-cyc/warp-iter
// vs only 3 SM-cyc of FFMA2 at Q=2). Fix: Q=8 queries per thread so one tile
// read feeds 24 FFMA2 (12 SM-cyc) -> fma-pipe becomes the binding resource
// (floor ~42.5K cyc ~ 23us). Block count restored by splitting the target set
// 8 ways (min is exact & order-free -> deterministic). Per-group combine via
// distinct-slot partial-min writes + last-block-done fixed-order reduction.

#define CD_B 8
#define CD_N 4096
#define CD_TPB 256
#define CD_Q 8
#define CD_QBLK (CD_TPB * CD_Q)          // 2048 queries per block
#define CD_NQB (CD_N / CD_QBLK)          // 2
#define CD_TSPLIT 8
#define CD_TPTS (CD_N / CD_TSPLIT)       // 512 targets per block
#define CD_TPAIRS (CD_TPTS / 2)          // 256 packed pairs
#define CD_NGRP (2 * CD_B * CD_NQB)      // 32 groups of CD_TSPLIT blocks

__device__ float g_pmin[CD_NGRP][CD_TSPLIT][CD_QBLK];  // per-query partial mins
__device__ float g_part[CD_NGRP];
__device__ unsigned int g_gcnt[CD_NGRP];
__device__ unsigned int g_fcnt;

typedef unsigned long long u64;

__device__ __forceinline__ u64 pack2(float v) {
    u64 r;
    unsigned int u = __float_as_uint(v);
    asm("mov.b64 %0, {%1, %1};" : "=l"(r) : "r"(u));
    return r;
}

__device__ __forceinline__ u64 fma2(u64 a, u64 b, u64 c) {
    u64 d;
    asm("fma.rn.f32x2 %0, %1, %2, %3;" : "=l"(d) : "l"(a), "l"(b), "l"(c));
    return d;
}

__device__ __forceinline__ void unpack2(u64 v, float& lo, float& hi) {
    unsigned int l, h;
    asm("mov.b64 {%0, %1}, %2;" : "=r"(l), "=r"(h) : "l"(v));
    lo = __uint_as_float(l);
    hi = __uint_as_float(h);
}

__global__ __launch_bounds__(CD_TPB)
void chamfer_kernel(const float* __restrict__ p1,
                    const float* __restrict__ p2,
                    float* __restrict__ out) {
    __shared__ float4 sy[CD_TPTS];   // pair-interleaved {y0e,y0o,y1e,y1o},{y2e,y2o,yde,ydo}
    __shared__ float red[CD_TPB];
    __shared__ int s_flag;

    const int tid  = threadIdx.x;
    const int qblk = blockIdx.x / CD_TSPLIT;
    const int ts   = blockIdx.x % CD_TSPLIT;
    const int b    = blockIdx.y;
    const int dir  = blockIdx.z;
    const int grp  = (dir * CD_B + b) * CD_NQB + qblk;

    const float* __restrict__ src = dir ? p2 : p1;
    const float* __restrict__ tgt = dir ? p1 : p2;

    // Load Q=8 query points; fold -2 into coords, pre-pack f32x2.
    float xd[CD_Q];
    u64 xq0[CD_Q], xq1[CD_Q], xq2[CD_Q];
    float mlo[CD_Q], mhi[CD_Q];
    #pragma unroll
    for (int q = 0; q < CD_Q; q++) {
        const int i = qblk * CD_QBLK + q * CD_TPB + tid;
        const float* xp = src + ((size_t)b * CD_N + i) * 3;
        const float x0 = xp[0], x1 = xp[1], x2 = xp[2];
        xd[q]  = x0 * x0 + x1 * x1 + x2 * x2;
        xq0[q] = pack2(-2.0f * x0);
        xq1[q] = pack2(-2.0f * x1);
        xq2[q] = pack2(-2.0f * x2);
        mlo[q] = 3.402823466e38f;
        mhi[q] = 3.402823466e38f;
    }

    // Build this block's 512-point target tile (one pair per thread).
    {
        const float* yp = tgt + ((size_t)b * CD_N + ts * CD_TPTS + 2 * tid) * 3;
        float e0 = yp[0], e1 = yp[1], e2 = yp[2];
        float o0 = yp[3], o1 = yp[4], o2 = yp[5];
        sy[2 * tid]     = make_float4(e0, o0, e1, o1);
        sy[2 * tid + 1] = make_float4(e2, o2,
                                      e0 * e0 + e1 * e1 + e2 * e2,
                                      o0 * o0 + o1 * o1 + o2 * o2);
    }
    __syncthreads();

    const ulonglong2* __restrict__ syu = reinterpret_cast<const ulonglong2*>(sy);

    #pragma unroll 4
    for (int p = 0; p < CD_TPAIRS; p++) {
        ulonglong2 A  = syu[2 * p];      // y0 pair, y1 pair
        ulonglong2 Bv = syu[2 * p + 1];  // y2 pair, yd pair
        #pragma unroll
        for (int q = 0; q < CD_Q; q++) {
            u64 d = fma2(xq2[q], Bv.x, Bv.y);
            d = fma2(xq1[q], A.y, d);
            d = fma2(xq0[q], A.x, d);
            float dlo, dhi;
            unpack2(d, dlo, dhi);
            mlo[q] = fminf(mlo[q], dlo);
            mhi[q] = fminf(mhi[q], dhi);
        }
    }

    // Write per-query partial mins (xd folded in) to distinct slots.
    #pragma unroll
    for (int q = 0; q < CD_Q; q++)
        g_pmin[grp][ts][q * CD_TPB + tid] = fminf(mlo[q], mhi[q]) + xd[q];

    __threadfence();
    if (tid == 0) {
        unsigned int t = atomicAdd(&g_gcnt[grp], 1u);
        s_flag = (t == CD_TSPLIT - 1);
    }
    __syncthreads();

    if (s_flag) {
        // Last block of the group: min across target splits, fixed-order sum.
        float acc = 0.0f;
        #pragma unroll
        for (int q = 0; q < CD_Q; q++) {
            const int qi = q * CD_TPB + tid;
            float v = g_pmin[grp][0][qi];
            #pragma unroll
            for (int t2 = 1; t2 < CD_TSPLIT; t2++)
                v = fminf(v, g_pmin[grp][t2][qi]);
            acc += v;
        }
        red[tid] = acc;
        __syncthreads();
        #pragma unroll
        for (int s = CD_TPB / 2; s > 0; s >>= 1) {
            if (tid < s) red[tid] += red[tid + s];
            __syncthreads();
        }
        if (tid == 0) {
            g_part[grp] = red[0];
            g_gcnt[grp] = 0;                       // reset for graph replay
            __threadfence();
            unsigned int t = atomicAdd(&g_fcnt, 1u);
            s_flag = (t == CD_NGRP - 1);
        }
        __syncthreads();

        if (s_flag) {
            // Final: fixed-order sum of 32 group partials.
            float v = (tid < CD_NGRP) ? g_part[tid] : 0.0f;
            red[tid] = v;
            __syncthreads();
            #pragma unroll
            for (int s = CD_TPB / 2; s > 0; s >>= 1) {
                if (tid < s) red[tid] += red[tid + s];
                __syncthreads();
            }
            if (tid == 0) {
                out[0] = red[0] * (1.0f / ((float)CD_B * (float)CD_N));
                g_fcnt = 0;                        // reset for graph replay
            }
        }
    }
}

extern "C" void kernel_launch(void* const* d_in, const int* in_sizes, int n_in,
                              void* d_out, int out_size) {
    (void)in_sizes; (void)n_in; (void)out_size;
    const float* p1 = (const float*)d_in[0];
    const float* p2 = (const float*)d_in[1];
    float* out = (float*)d_out;

    dim3 grid(CD_NQB * CD_TSPLIT, CD_B, 2);   // 16 x 8 x 2 = 256 blocks
    chamfer_kernel<<<grid, CD_TPB>>>(p1, p2, out);
}

// round 4
// speedup vs baseline: 1.7783x; 1.1019x over previous
#include <cuda_runtime.h>
#include <cuda_bf16.h>

// ChamferDistance: B=8, N=4096, D=3.
// Round 4: round-3 was latency/issue-bound (occ 3.25 warps/SMSP, issue 49%,
// no pipe >42%). Same packed-FFMA2 inner loop, but: 128-thread blocks,
// 1024 blocks (4 qblk x 16 tsplit x 8 batch x 2 dir) -> ~6 warps/SMSP for
// latency hiding and near-uniform per-SM work. xd parked in smem to trim
// register pressure. Deterministic cross-split combine via distinct slots +
// last-block-done fixed-order reductions.

#define CD_B 8
#define CD_N 4096
#define CD_TPB 128
#define CD_Q 8
#define CD_QBLK (CD_TPB * CD_Q)          // 1024 queries per block
#define CD_NQB (CD_N / CD_QBLK)          // 4
#define CD_TSPLIT 16
#define CD_TPTS (CD_N / CD_TSPLIT)       // 256 targets per block
#define CD_TPAIRS (CD_TPTS / 2)          // 128 packed pairs
#define CD_NGRP (2 * CD_B * CD_NQB)      // 64 groups of CD_TSPLIT blocks

__device__ float g_pmin[CD_NGRP][CD_TSPLIT][CD_QBLK];
__device__ float g_part[CD_NGRP];
__device__ unsigned int g_gcnt[CD_NGRP];
__device__ unsigned int g_fcnt;

typedef unsigned long long u64;

__device__ __forceinline__ u64 pack2(float v) {
    u64 r;
    unsigned int u = __float_as_uint(v);
    asm("mov.b64 %0, {%1, %1};" : "=l"(r) : "r"(u));
    return r;
}

__device__ __forceinline__ u64 fma2(u64 a, u64 b, u64 c) {
    u64 d;
    asm("fma.rn.f32x2 %0, %1, %2, %3;" : "=l"(d) : "l"(a), "l"(b), "l"(c));
    return d;
}

__device__ __forceinline__ void unpack2(u64 v, float& lo, float& hi) {
    unsigned int l, h;
    asm("mov.b64 {%0, %1}, %2;" : "=r"(l), "=r"(h) : "l"(v));
    lo = __uint_as_float(l);
    hi = __uint_as_float(h);
}

__global__ __launch_bounds__(CD_TPB)
void chamfer_kernel(const float* __restrict__ p1,
                    const float* __restrict__ p2,
                    float* __restrict__ out) {
    __shared__ float4 sy[CD_TPTS];      // pair-interleaved tile (4KB)
    __shared__ float s_xd[CD_Q][CD_TPB];
    __shared__ float red[CD_TPB];
    __shared__ int s_flag;

    const int tid  = threadIdx.x;
    const int ts   = blockIdx.x % CD_TSPLIT;
    const int qblk = blockIdx.x / CD_TSPLIT;
    const int b    = blockIdx.y;
    const int dir  = blockIdx.z;
    const int grp  = (dir * CD_B + b) * CD_NQB + qblk;

    const float* __restrict__ src = dir ? p2 : p1;
    const float* __restrict__ tgt = dir ? p1 : p2;

    // Q=8 query points; fold -2 into packed coords; xd parked in smem.
    u64 xq0[CD_Q], xq1[CD_Q], xq2[CD_Q];
    float mlo[CD_Q], mhi[CD_Q];
    #pragma unroll
    for (int q = 0; q < CD_Q; q++) {
        const int i = qblk * CD_QBLK + q * CD_TPB + tid;
        const float* xp = src + ((size_t)b * CD_N + i) * 3;
        const float x0 = xp[0], x1 = xp[1], x2 = xp[2];
        s_xd[q][tid] = x0 * x0 + x1 * x1 + x2 * x2;
        xq0[q] = pack2(-2.0f * x0);
        xq1[q] = pack2(-2.0f * x1);
        xq2[q] = pack2(-2.0f * x2);
        mlo[q] = 3.402823466e38f;
        mhi[q] = 3.402823466e38f;
    }

    // One target pair per thread into the pair-interleaved tile.
    {
        const float* yp = tgt + ((size_t)b * CD_N + ts * CD_TPTS + 2 * tid) * 3;
        float e0 = yp[0], e1 = yp[1], e2 = yp[2];
        float o0 = yp[3], o1 = yp[4], o2 = yp[5];
        sy[2 * tid]     = make_float4(e0, o0, e1, o1);
        sy[2 * tid + 1] = make_float4(e2, o2,
                                      e0 * e0 + e1 * e1 + e2 * e2,
                                      o0 * o0 + o1 * o1 + o2 * o2);
    }
    __syncthreads();

    const ulonglong2* __restrict__ syu = reinterpret_cast<const ulonglong2*>(sy);

    #pragma unroll 4
    for (int p = 0; p < CD_TPAIRS; p++) {
        ulonglong2 A  = syu[2 * p];      // y0 pair, y1 pair
        ulonglong2 Bv = syu[2 * p + 1];  // y2 pair, yd pair
        #pragma unroll
        for (int q = 0; q < CD_Q; q++) {
            u64 d = fma2(xq2[q], Bv.x, Bv.y);
            d = fma2(xq1[q], A.y, d);
            d = fma2(xq0[q], A.x, d);
            float dlo, dhi;
            unpack2(d, dlo, dhi);
            mlo[q] = fminf(mlo[q], dlo);
            mhi[q] = fminf(mhi[q], dhi);
        }
    }

    // Per-query partial mins (xd folded) to distinct slots.
    #pragma unroll
    for (int q = 0; q < CD_Q; q++)
        g_pmin[grp][ts][q * CD_TPB + tid] = fminf(mlo[q], mhi[q]) + s_xd[q][tid];

    __threadfence();
    if (tid == 0) {
        unsigned int t = atomicAdd(&g_gcnt[grp], 1u);
        s_flag = (t == CD_TSPLIT - 1);
    }
    __syncthreads();

    if (s_flag) {
        // Last block of the group: min across 16 target splits, fixed-order sum.
        float acc = 0.0f;
        #pragma unroll
        for (int q = 0; q < CD_Q; q++) {
            const int qi = q * CD_TPB + tid;
            float v = g_pmin[grp][0][qi];
            #pragma unroll
            for (int t2 = 1; t2 < CD_TSPLIT; t2++)
                v = fminf(v, g_pmin[grp][t2][qi]);
            acc += v;
        }
        red[tid] = acc;
        __syncthreads();
        #pragma unroll
        for (int s = CD_TPB / 2; s > 0; s >>= 1) {
            if (tid < s) red[tid] += red[tid + s];
            __syncthreads();
        }
        if (tid == 0) {
            g_part[grp] = red[0];
            g_gcnt[grp] = 0;                       // reset for graph replay
            __threadfence();
            unsigned int t = atomicAdd(&g_fcnt, 1u);
            s_flag = (t == CD_NGRP - 1);
        }
        __syncthreads();

        if (s_flag) {
            // Final: fixed-order sum of 64 group partials.
            float v = (tid < CD_NGRP) ? g_part[tid] : 0.0f;
            red[tid] = v;
            __syncthreads();
            #pragma unroll
            for (int s = CD_TPB / 2; s > 0; s >>= 1) {
                if (tid < s) red[tid] += red[tid + s];
                __syncthreads();
            }
            if (tid == 0) {
                out[0] = red[0] * (1.0f / ((float)CD_B * (float)CD_N));
                g_fcnt = 0;                        // reset for graph replay
            }
        }
    }
}

extern "C" void kernel_launch(void* const* d_in, const int* in_sizes, int n_in,
                              void* d_out, int out_size) {
    (void)in_sizes; (void)n_in; (void)out_size;
    const float* p1 = (const float*)d_in[0];
    const float* p2 = (const float*)d_in[1];
    float* out = (float*)d_out;

    dim3 grid(CD_NQB * CD_TSPLIT, CD_B, 2);   // 64 x 8 x 2 = 1024 blocks
    chamfer_kernel<<<grid, CD_TPB>>>(p1, p2, out);
}